// round 3
// baseline (speedup 1.0000x reference)
#include <cuda_runtime.h>
#include <math.h>

#define NB      8192
#define TILE_B  32
#define NT      256
#define SMEM_FLOATS 24836

typedef unsigned long long ull;

__device__ __forceinline__ float silu_f(float x){
    return x * (1.0f / (1.0f + __expf(-x)));
}

// ---- packed f32x2 helpers (sm_103a FFMA2 path; ptxas never auto-fuses) ----
__device__ __forceinline__ ull pack2(float lo, float hi){
    ull r; asm("mov.b64 %0, {%1,%2};" : "=l"(r) : "f"(lo), "f"(hi)); return r;
}
__device__ __forceinline__ void fma2(ull& d, ull a, ull b){
    asm("fma.rn.f32x2 %0, %1, %2, %0;" : "+l"(d) : "l"(a), "l"(b));
}
__device__ __forceinline__ float hsum2(ull v){
    float lo, hi; asm("mov.b64 {%0,%1}, %2;" : "=f"(lo), "=f"(hi) : "l"(v));
    return lo + hi;
}

// Warp-cooperative top-6 of 64 values (2 per lane). Tie-break: lower index.
__device__ __forceinline__ void topk6(float p0, float p1, int lane, int* sel, float* sv){
    #pragma unroll
    for (int t = 0; t < 6; ++t){
        float v = p0; int id = lane;
        if (p1 > v){ v = p1; id = lane + 32; }
        #pragma unroll
        for (int off = 16; off > 0; off >>= 1){
            float ov = __shfl_xor_sync(0xffffffffu, v, off);
            int  oid = __shfl_xor_sync(0xffffffffu, id, off);
            if (ov > v || (ov == v && oid < id)){ v = ov; id = oid; }
        }
        sv[t] = v; sel[t] = id;
        if (id == lane)           p0 = -INFINITY;
        else if (id == lane + 32) p1 = -INFINITY;
    }
}

// One row: gumbel perturb, top-5 select, one-hot write, exact-PL log-prob.
__device__ float row_topk_lp(const float* __restrict__ u,
                             const float* __restrict__ lg,
                             float m, float Z,
                             float* __restrict__ cfg,
                             int lane, int* selOut)
{
    float l0 = lg[lane], l1 = lg[lane + 32];
    float u0 = fmaxf(u[lane],      1e-10f);
    float u1 = fmaxf(u[lane + 32], 1e-10f);
    float p0 = l0 - __logf(-__logf(u0));
    float p1 = l1 - __logf(-__logf(u1));
    int sel[6]; float sv[6];
    topk6(p0, p1, lane, sel, sv);
    if (sv[4] - sv[5] < 1e-4f){
        p0 = l0 - (float)log(-log((double)u0));
        p1 = l1 - (float)log(-log((double)u1));
        topk6(p0, p1, lane, sel, sv);
    }
    float c0 = 0.f, c1 = 0.f;
    #pragma unroll
    for (int t = 0; t < 5; ++t){
        c0 += (sel[t] == lane)      ? 1.f : 0.f;
        c1 += (sel[t] == lane + 32) ? 1.f : 0.f;
    }
    cfg[lane]      = c0;
    cfg[lane + 32] = c1;

    // exact PL over 5! orderings via 2^5-subset DP
    float lsum = 0.f, e[5];
    #pragma unroll
    for (int t = 0; t < 5; ++t){
        float lt = lg[sel[t]];
        lsum += lt;
        e[t] = expf(lt - m);
    }
    float f[32];
    f[31] = 1.f;
    #pragma unroll
    for (int mask = 30; mask >= 0; --mask){
        float Em = 0.f, s = 0.f;
        #pragma unroll
        for (int t = 0; t < 5; ++t){
            if (mask & (1 << t)) Em += e[t];
            else                 s  += f[mask | (1 << t)];
        }
        f[mask] = __fdividef(s, Z - Em);
    }
    #pragma unroll
    for (int t = 0; t < 5; ++t) selOut[t] = sel[t];
    return lsum - 5.f * m + logf(f[0]);
}

__global__ __launch_bounds__(NT, 2)
void pcf_kernel(const float* __restrict__ Ua, const float* __restrict__ Ub,
                const float* __restrict__ AL,
                const float* __restrict__ W1, const float* __restrict__ b1,
                const float* __restrict__ W2, const float* __restrict__ b2,
                const float* __restrict__ V1, const float* __restrict__ c1,
                const float* __restrict__ V2, const float* __restrict__ c2,
                const float* __restrict__ V3, const float* __restrict__ c3,
                float* __restrict__ out)
{
    extern __shared__ float sm[];
    float* s_alog = sm;                    // 64
    float* s_scal = sm + 64;               // 4
    int*   s_sela = (int*)(sm + 68);       // 160
    float* s_lpa  = sm + 228;              // 32  -> 260 (16B aligned)
    float* s_h    = sm + 260;              // 32x128
    float* s_x    = s_h  + TILE_B * 128;   // 32x64
    float* s_z1   = s_x  + TILE_B * 64;    // 32x256
    float* s_z2   = s_z1 + TILE_B * 256;   // 32x256
    float* s_blog = s_z2 + TILE_B * 256;   // 32x64

    const int tid  = threadIdx.x;
    const int lane = tid & 31;
    const int wid  = tid >> 5;
    const int row0 = blockIdx.x * TILE_B;

    // --- alpha logits stats (block-constant) ---
    if (wid == 0){
        float l0 = AL[lane], l1 = AL[lane + 32];
        s_alog[lane] = l0; s_alog[lane + 32] = l1;
        float mv = fmaxf(l0, l1);
        #pragma unroll
        for (int off = 16; off > 0; off >>= 1)
            mv = fmaxf(mv, __shfl_xor_sync(0xffffffffu, mv, off));
        float zv = expf(l0 - mv) + expf(l1 - mv);
        #pragma unroll
        for (int off = 16; off > 0; off >>= 1)
            zv += __shfl_xor_sync(0xffffffffu, zv, off);
        if (lane == 0){ s_scal[0] = mv; s_scal[1] = zv; }
    }
    __syncthreads();
    const float ma = s_scal[0], Za = s_scal[1];

    // --- alpha selection + lp_a ---
    for (int rr = 0; rr < 4; ++rr){
        int r = wid * 4 + rr;
        int row = row0 + r;
        int sel[5];
        float lp = row_topk_lp(Ua + (size_t)row * 64, s_alog, ma, Za,
                               out + (size_t)row * 128, lane, sel);
        if (lane == 0){
            s_lpa[r] = lp;
            #pragma unroll
            for (int t = 0; t < 5; ++t) s_sela[r * 5 + t] = sel[t];
        }
    }
    __syncthreads();

    // --- h = silu(sum of 5 W1 rows + b1) ---
    for (int i = tid; i < TILE_B * 128; i += NT){
        int r = i >> 7, j = i & 127;
        float a = b1[j];
        #pragma unroll
        for (int t = 0; t < 5; ++t) a += W1[s_sela[r * 5 + t] * 128 + j];
        s_h[i] = silu_f(a);
    }
    __syncthreads();

    // --- ctx = h @ W2 + b2  (K=128, N=64), packed f32x2 ---
    {
        const int c = tid & 63, rg = tid >> 6;
        const float* Wp = W2 + c;
        ull acc[8];
        #pragma unroll
        for (int i = 0; i < 8; i++) acc[i] = 0ULL;
        for (int kb = 0; kb < 32; ++kb){
            const int k = kb * 4;
            ull w01 = pack2(Wp[(k+0)*64], Wp[(k+1)*64]);
            ull w23 = pack2(Wp[(k+2)*64], Wp[(k+3)*64]);
            #pragma unroll
            for (int i = 0; i < 8; i++){
                const ulonglong2 h2 = *reinterpret_cast<const ulonglong2*>(s_h + (rg*8 + i)*128 + k);
                fma2(acc[i], h2.x, w01);
                fma2(acc[i], h2.y, w23);
            }
        }
        float bb = b2[c];
        #pragma unroll
        for (int i = 0; i < 8; i++) s_x[(rg*8 + i)*64 + c] = hsum2(acc[i]) + bb;
    }
    __syncthreads();

    // --- z1 = silu(ctx @ V1[64:,:] + c1)  (K=64, N=256), 2 cols x 16 rows ---
    {
        const int cp = tid & 127;
        const int rh = tid >> 7;
        const float* Vp = V1 + 64 * 256 + 2 * cp;
        ull acc0[16], acc1[16];
        #pragma unroll
        for (int r = 0; r < 16; r++){ acc0[r] = 0ULL; acc1[r] = 0ULL; }
        float2 w0 = *(const float2*)(Vp + 0);
        float2 w1 = *(const float2*)(Vp + 256);
        float2 w2v = *(const float2*)(Vp + 512);
        float2 w3 = *(const float2*)(Vp + 768);
        const float* xs0 = s_x + rh * 16 * 64;
        for (int kb = 0; kb < 16; ++kb){
            ull a01 = pack2(w0.x, w1.x), a23 = pack2(w2v.x, w3.x);
            ull b01 = pack2(w0.y, w1.y), b23 = pack2(w2v.y, w3.y);
            float2 n0, n1, n2, n3;
            n0 = n1 = n2 = n3 = make_float2(0.f, 0.f);
            if (kb < 15){
                const float* q = Vp + (kb + 1) * 4 * 256;
                n0 = *(const float2*)(q + 0);   n1 = *(const float2*)(q + 256);
                n2 = *(const float2*)(q + 512); n3 = *(const float2*)(q + 768);
            }
            const float* xs = xs0 + kb * 4;
            #pragma unroll
            for (int r = 0; r < 16; r++){
                const ulonglong2 z = *reinterpret_cast<const ulonglong2*>(xs + r * 64);
                fma2(acc0[r], z.x, a01); fma2(acc0[r], z.y, a23);
                fma2(acc1[r], z.x, b01); fma2(acc1[r], z.y, b23);
            }
            w0 = n0; w1 = n1; w2v = n2; w3 = n3;
        }
        float bb0 = c1[2*cp], bb1 = c1[2*cp + 1];
        #pragma unroll
        for (int r = 0; r < 16; r++){
            float2 o;
            o.x = silu_f(hsum2(acc0[r]) + bb0);
            o.y = silu_f(hsum2(acc1[r]) + bb1);
            *reinterpret_cast<float2*>(s_z1 + (rh*16 + r)*256 + 2*cp) = o;
        }
    }
    __syncthreads();

    // --- z2 = silu(z1 @ V2 + c2)  (K=256, N=256), 2 cols x 16 rows ---
    {
        const int cp = tid & 127;
        const int rh = tid >> 7;
        const float* Vp = V2 + 2 * cp;
        ull acc0[16], acc1[16];
        #pragma unroll
        for (int r = 0; r < 16; r++){ acc0[r] = 0ULL; acc1[r] = 0ULL; }
        float2 w0 = *(const float2*)(Vp + 0);
        float2 w1 = *(const float2*)(Vp + 256);
        float2 w2v = *(const float2*)(Vp + 512);
        float2 w3 = *(const float2*)(Vp + 768);
        const float* zs0 = s_z1 + rh * 16 * 256;
        for (int kb = 0; kb < 64; ++kb){
            ull a01 = pack2(w0.x, w1.x), a23 = pack2(w2v.x, w3.x);
            ull b01 = pack2(w0.y, w1.y), b23 = pack2(w2v.y, w3.y);
            float2 n0, n1, n2, n3;
            n0 = n1 = n2 = n3 = make_float2(0.f, 0.f);
            if (kb < 63){
                const float* q = Vp + (kb + 1) * 4 * 256;
                n0 = *(const float2*)(q + 0);   n1 = *(const float2*)(q + 256);
                n2 = *(const float2*)(q + 512); n3 = *(const float2*)(q + 768);
            }
            const float* zs = zs0 + kb * 4;
            #pragma unroll
            for (int r = 0; r < 16; r++){
                const ulonglong2 z = *reinterpret_cast<const ulonglong2*>(zs + r * 256);
                fma2(acc0[r], z.x, a01); fma2(acc0[r], z.y, a23);
                fma2(acc1[r], z.x, b01); fma2(acc1[r], z.y, b23);
            }
            w0 = n0; w1 = n1; w2v = n2; w3 = n3;
        }
        float bb0 = c2[2*cp], bb1 = c2[2*cp + 1];
        #pragma unroll
        for (int r = 0; r < 16; r++){
            float2 o;
            o.x = silu_f(hsum2(acc0[r]) + bb0);
            o.y = silu_f(hsum2(acc1[r]) + bb1);
            *reinterpret_cast<float2*>(s_z2 + (rh*16 + r)*256 + 2*cp) = o;
        }
    }
    __syncthreads();

    // --- beta_logits = z2 @ V3 + c3  (K=256, N=64), packed f32x2 ---
    {
        const int c = tid & 63, rg = tid >> 6;
        const float* Vp = V3 + c;
        ull acc[8];
        #pragma unroll
        for (int i = 0; i < 8; i++) acc[i] = 0ULL;
        for (int kb = 0; kb < 64; ++kb){
            const int k = kb * 4;
            ull w01 = pack2(Vp[(k+0)*64], Vp[(k+1)*64]);
            ull w23 = pack2(Vp[(k+2)*64], Vp[(k+3)*64]);
            #pragma unroll
            for (int i = 0; i < 8; i++){
                const ulonglong2 z2v = *reinterpret_cast<const ulonglong2*>(s_z2 + (rg*8 + i)*256 + k);
                fma2(acc[i], z2v.x, w01);
                fma2(acc[i], z2v.y, w23);
            }
        }
        float bb = c3[c];
        #pragma unroll
        for (int i = 0; i < 8; i++) s_blog[(rg*8 + i)*64 + c] = hsum2(acc[i]) + bb;
    }
    __syncthreads();

    // --- beta selection + lp_b + final output ---
    for (int rr = 0; rr < 4; ++rr){
        int r = wid * 4 + rr;
        int row = row0 + r;
        const float* lg = s_blog + r * 64;
        float l0 = lg[lane], l1 = lg[lane + 32];
        float mv = fmaxf(l0, l1);
        #pragma unroll
        for (int off = 16; off > 0; off >>= 1)
            mv = fmaxf(mv, __shfl_xor_sync(0xffffffffu, mv, off));
        float zv = expf(l0 - mv) + expf(l1 - mv);
        #pragma unroll
        for (int off = 16; off > 0; off >>= 1)
            zv += __shfl_xor_sync(0xffffffffu, zv, off);
        int sel[5];
        float lpb = row_topk_lp(Ub + (size_t)row * 64, lg, mv, zv,
                                out + (size_t)row * 128 + 64, lane, sel);
        if (lane == 0)
            out[(size_t)NB * 128 + row] = s_lpa[r] + lpb;
    }
}

extern "C" void kernel_launch(void* const* d_in, const int* in_sizes, int n_in,
                              void* d_out, int out_size)
{
    (void)in_sizes; (void)n_in; (void)out_size;
    const float* Ua = (const float*)d_in[0];
    const float* Ub = (const float*)d_in[1];
    const float* AL = (const float*)d_in[2];
    const float* W1 = (const float*)d_in[3];
    const float* b1 = (const float*)d_in[4];
    const float* W2 = (const float*)d_in[5];
    const float* b2 = (const float*)d_in[6];
    const float* V1 = (const float*)d_in[7];
    const float* c1 = (const float*)d_in[8];
    const float* V2 = (const float*)d_in[9];
    const float* c2 = (const float*)d_in[10];
    const float* V3 = (const float*)d_in[11];
    const float* c3 = (const float*)d_in[12];
    float* out = (float*)d_out;

    const int smem_bytes = SMEM_FLOATS * (int)sizeof(float);
    cudaFuncSetAttribute(pcf_kernel, cudaFuncAttributeMaxDynamicSharedMemorySize, smem_bytes);
    pcf_kernel<<<NB / TILE_B, NT, smem_bytes>>>(Ua, Ub, AL, W1, b1, W2, b2,
                                                V1, c1, V2, c2, V3, c3, out);
}